// round 9
// baseline (speedup 1.0000x reference)
#include <cuda_runtime.h>
#include <math.h>

#define IGNORE_LABEL (-100LL)
#define MAXB 64

// zero at module load; the finalizing block resets everything after use,
// so each launch / graph replay starts from zeroed scratch.
__device__ double g_tasksum[MAXB];
__device__ int    g_correct[MAXB];
__device__ int    g_valid[MAXB];
__device__ int    g_labels_is64;
__device__ unsigned int g_done;

__device__ __forceinline__ float frcp_fast(float t) {
    float r;
    asm("rcp.approx.ftz.f32 %0, %1;" : "=f"(r) : "f"(t));
    return r;
}

__device__ __forceinline__ float smap(float v) {
    // s(x) = x<0 ? 1/(1-x) : x+1
    float r = frcp_fast(1.0f - v);
    return v < 0.0f ? r : v + 1.0f;
}

// tiny: decide whether labels buffer is int64 or int32.
// Reads first 32 entries as int64 (256B, in-bounds under either dtype).
__global__ void probe_kernel(const void* __restrict__ labels, int V) {
    long long v = ((const long long*)labels)[threadIdx.x];
    bool okv = (v >= 0 && v < (long long)V) || v == IGNORE_LABEL;
    unsigned m = __ballot_sync(0xffffffffu, okv);
    if (threadIdx.x == 0) g_labels_is64 = (m == 0xffffffffu);
}

// one block per token row; the last block to finish also computes the final loss.
// launch_bounds(256,4): cap 4 blocks/SM -> 64 regs/thread available, so the
// unroll-8 body can keep 8 independent LDG.128 in flight (MLP_eff ~ 8).
__global__ void __launch_bounds__(256, 4) row_kernel(
        const float* __restrict__ logits,
        const void* __restrict__ labels_raw,
        const float* __restrict__ qh,
        const float* __restrict__ qc,
        float* __restrict__ out,
        int V, int Lseq, int Bn) {
    const int row = blockIdx.x;
    const int tid = threadIdx.x;
    const int nt  = blockDim.x;
    const float* __restrict__ x = logits + (size_t)row * V;

    __shared__ float     ssum[256];
    __shared__ float     smaxv[256];
    __shared__ int       sidx[256];
    __shared__ float     sh_xl;
    __shared__ long long sh_label;
    __shared__ int       sh_need_scan;

    if (tid == 0) {
        long long label;
        if (g_labels_is64) label = ((const long long*)labels_raw)[row];
        else               label = (long long)((const int*)labels_raw)[row];
        sh_label = label;
        int safe = (label >= 0 && label < (long long)V) ? (int)label : 0;
        sh_xl = x[safe];
        sh_need_scan = 0;
    }
    __syncthreads();
    const float xl = sh_xl;

    float sumA = 0.f, sumB = 0.f;
    float vmaxA = -INFINITY, vmaxB = -INFINITY;

    const int V4 = V >> 2;
    const float4* __restrict__ x4 = (const float4*)x;

    // main loop: 8 independent 16B loads in flight per thread
    int i = tid;
    #pragma unroll 1
    for (; i + 7 * nt < V4; i += 8 * nt) {
        float4 v0 = __ldg(&x4[i + 0 * nt]);
        float4 v1 = __ldg(&x4[i + 1 * nt]);
        float4 v2 = __ldg(&x4[i + 2 * nt]);
        float4 v3 = __ldg(&x4[i + 3 * nt]);
        float4 v4 = __ldg(&x4[i + 4 * nt]);
        float4 v5 = __ldg(&x4[i + 5 * nt]);
        float4 v6 = __ldg(&x4[i + 6 * nt]);
        float4 v7 = __ldg(&x4[i + 7 * nt]);
        sumA += smap(v0.x) + smap(v0.y); sumB += smap(v0.z) + smap(v0.w);
        sumA += smap(v1.x) + smap(v1.y); sumB += smap(v1.z) + smap(v1.w);
        sumA += smap(v2.x) + smap(v2.y); sumB += smap(v2.z) + smap(v2.w);
        sumA += smap(v3.x) + smap(v3.y); sumB += smap(v3.z) + smap(v3.w);
        sumA += smap(v4.x) + smap(v4.y); sumB += smap(v4.z) + smap(v4.w);
        sumA += smap(v5.x) + smap(v5.y); sumB += smap(v5.z) + smap(v5.w);
        sumA += smap(v6.x) + smap(v6.y); sumB += smap(v6.z) + smap(v6.w);
        sumA += smap(v7.x) + smap(v7.y); sumB += smap(v7.z) + smap(v7.w);
        vmaxA = fmaxf(vmaxA, fmaxf(fmaxf(v0.x, v0.y), fmaxf(v0.z, v0.w)));
        vmaxB = fmaxf(vmaxB, fmaxf(fmaxf(v1.x, v1.y), fmaxf(v1.z, v1.w)));
        vmaxA = fmaxf(vmaxA, fmaxf(fmaxf(v2.x, v2.y), fmaxf(v2.z, v2.w)));
        vmaxB = fmaxf(vmaxB, fmaxf(fmaxf(v3.x, v3.y), fmaxf(v3.z, v3.w)));
        vmaxA = fmaxf(vmaxA, fmaxf(fmaxf(v4.x, v4.y), fmaxf(v4.z, v4.w)));
        vmaxB = fmaxf(vmaxB, fmaxf(fmaxf(v5.x, v5.y), fmaxf(v5.z, v5.w)));
        vmaxA = fmaxf(vmaxA, fmaxf(fmaxf(v6.x, v6.y), fmaxf(v6.z, v6.w)));
        vmaxB = fmaxf(vmaxB, fmaxf(fmaxf(v7.x, v7.y), fmaxf(v7.z, v7.w)));
    }
    for (; i < V4; i += nt) {
        float4 v = __ldg(&x4[i]);
        sumA += smap(v.x) + smap(v.y);
        sumB += smap(v.z) + smap(v.w);
        vmaxA = fmaxf(vmaxA, fmaxf(fmaxf(v.x, v.y), fmaxf(v.z, v.w)));
    }
    for (int j = (V4 << 2) + tid; j < V; j += nt) {
        float v = __ldg(&x[j]);
        sumA += smap(v);
        vmaxA = fmaxf(vmaxA, v);
    }

    ssum[tid]  = sumA + sumB;
    smaxv[tid] = fmaxf(vmaxA, vmaxB);
    __syncthreads();
    for (int s = nt >> 1; s > 0; s >>= 1) {
        if (tid < s) {
            ssum[tid]  += ssum[tid + s];
            smaxv[tid]  = fmaxf(smaxv[tid], smaxv[tid + s]);
        }
        __syncthreads();
    }

    // rare path: label attains the row max -> need exact first-index argmax
    if (tid == 0) {
        long long label = sh_label;
        if (label >= 0 && label < (long long)V && xl == smaxv[0])
            sh_need_scan = 1;
    }
    __syncthreads();

    int arg_idx = -1;
    if (sh_need_scan) {
        float lmax = -INFINITY;
        int   lidx = 0x7fffffff;
        for (int k = tid; k < V4; k += nt) {
            float4 v = __ldg(&x4[k]);
            int base = k << 2;
            if (v.x > lmax) { lmax = v.x; lidx = base + 0; }
            if (v.y > lmax) { lmax = v.y; lidx = base + 1; }
            if (v.z > lmax) { lmax = v.z; lidx = base + 2; }
            if (v.w > lmax) { lmax = v.w; lidx = base + 3; }
        }
        for (int k = (V4 << 2) + tid; k < V; k += nt) {
            float v = __ldg(&x[k]);
            if (v > lmax) { lmax = v; lidx = k; }
        }
        smaxv[tid] = lmax;   // safe: sum tree already consumed; ssum[0] untouched
        sidx[tid]  = lidx;
        __syncthreads();
        for (int s = nt >> 1; s > 0; s >>= 1) {
            if (tid < s) {
                float mv = smaxv[tid + s]; int mi = sidx[tid + s];
                if (mv > smaxv[tid] || (mv == smaxv[tid] && mi < sidx[tid])) {
                    smaxv[tid] = mv; sidx[tid] = mi;
                }
            }
            __syncthreads();
        }
        arg_idx = sidx[0];
    }

    if (tid == 0) {
        long long label = sh_label;
        if (label >= 0 && label < (long long)V) {
            int b = row / Lseq;
            double xd = (double)xl;
            double sl = xd < 0.0 ? 1.0 / (1.0 - xd + 1e-30) : xd + 1.0;
            double pt = log((double)ssum[0]) - log(sl);   // -log(s_label/sum)
            atomicAdd(&g_tasksum[b], pt);
            atomicAdd(&g_valid[b], 1);
            bool correct = sh_need_scan && ((long long)arg_idx == label);
            if (correct) atomicAdd(&g_correct[b], 1);
        }

        // ---- last-block finalize ----
        __threadfence();
        unsigned int ticket = atomicAdd(&g_done, 1u);
        if (ticket == gridDim.x - 1) {
            volatile double* vsum = g_tasksum;
            volatile int*    vval = g_valid;
            volatile int*    vcor = g_correct;
            float Ltask = 0.f, lh = 0.f, lc = 0.f;
            for (int b = 0; b < Bn; b++) {
                int    nv = vval[b];
                int    nc = vcor[b];
                double ts = vsum[b];
                float cnt = (float)(nv > 1 ? nv : 1);
                Ltask += (float)ts / cnt;
                float t = (nc == nv) ? 1.f : 0.f;
                float xh = qh[b];
                lh += fmaxf(xh, 0.f) - xh * t + log1pf(expf(-fabsf(xh)));
                float tc = 1.f / (1.f + expf(-xh));
                float xc = qc[b];
                lc += fmaxf(xc, 0.f) - xc * tc + log1pf(expf(-fabsf(xc)));
                vsum[b] = 0.0;
                vval[b] = 0;
                vcor[b] = 0;
            }
            Ltask /= (float)Bn;
            float Lhalt = 0.5f * (lh / (float)Bn + lc / (float)Bn);
            out[0] = Ltask + Lhalt;
            __threadfence();
            g_done = 0;
        }
    }
}

extern "C" void kernel_launch(void* const* d_in, const int* in_sizes, int n_in,
                              void* d_out, int out_size) {
    // Identify inputs by size, not position.
    int li = 0;
    for (int i = 1; i < n_in; i++) if (in_sizes[i] > in_sizes[li]) li = i;
    int lab = -1;
    for (int i = 0; i < n_in; i++) {
        if (i == li) continue;
        if (lab < 0 || in_sizes[i] > in_sizes[lab]) lab = i;
    }
    int qi[2]; int nq = 0;
    for (int i = 0; i < n_in && nq < 2; i++) {
        if (i != li && i != lab) qi[nq++] = i;
    }

    const float* logits = (const float*)d_in[li];
    const void*  labels = d_in[lab];
    const float* qh     = (const float*)d_in[qi[0]];
    const float* qc     = (const float*)d_in[qi[1]];

    const int Bn   = in_sizes[qi[0]];
    const int rows = in_sizes[lab];
    const int Lseq = rows / Bn;
    const int V    = (int)((long long)in_sizes[li] / rows);

    probe_kernel<<<1, 32>>>(labels, V);
    row_kernel<<<rows, 256>>>(logits, labels, qh, qc, (float*)d_out, V, Lseq, Bn);
}

// round 10
// speedup vs baseline: 1.1034x; 1.1034x over previous
#include <cuda_runtime.h>
#include <math.h>

#define IGNORE_LABEL (-100LL)
#define MAXB 64

// zero at module load; the finalizing block resets everything after use,
// so each launch / graph replay starts from zeroed scratch.
__device__ double g_tasksum[MAXB];
__device__ int    g_correct[MAXB];
__device__ int    g_valid[MAXB];
__device__ int    g_labels_is64;
__device__ unsigned int g_done;

__device__ __forceinline__ float frcp_fast(float t) {
    float r;
    asm("rcp.approx.ftz.f32 %0, %1;" : "=f"(r) : "f"(t));
    return r;
}

__device__ __forceinline__ float smap(float v) {
    // s(x) = x<0 ? 1/(1-x) : x+1
    float r = frcp_fast(1.0f - v);
    return v < 0.0f ? r : v + 1.0f;
}

// tiny: decide whether labels buffer is int64 or int32.
// Reads first 32 entries as int64 (256B, in-bounds under either dtype).
__global__ void probe_kernel(const void* __restrict__ labels, int V) {
    long long v = ((const long long*)labels)[threadIdx.x];
    bool okv = (v >= 0 && v < (long long)V) || v == IGNORE_LABEL;
    unsigned m = __ballot_sync(0xffffffffu, okv);
    if (threadIdx.x == 0) g_labels_is64 = (m == 0xffffffffu);
}

// one block per token row; the last block to finish also computes the final loss.
__global__ void __launch_bounds__(256) row_kernel(
        const float* __restrict__ logits,
        const void* __restrict__ labels_raw,
        const float* __restrict__ qh,
        const float* __restrict__ qc,
        float* __restrict__ out,
        int V, int Lseq, int Bn) {
    const int row = blockIdx.x;
    const int tid = threadIdx.x;
    const int nt  = blockDim.x;
    const int lane = tid & 31;
    const int wid  = tid >> 5;
    const float* __restrict__ x = logits + (size_t)row * V;

    __shared__ float wsum[8];
    __shared__ float wmax[8];
    __shared__ float smaxv[256];
    __shared__ int   sidx[256];
    __shared__ int   sh_need_scan;
    __shared__ float sh_sum;
    __shared__ float sh_max;

    // ---- scan starts immediately: no label read, no syncthreads up front ----
    float sumA = 0.f, sumB = 0.f;
    float vmax = -INFINITY;

    const int V4 = V >> 2;
    const float4* __restrict__ x4 = (const float4*)x;
    #pragma unroll 4
    for (int i = tid; i < V4; i += nt) {
        float4 v = __ldcs(&x4[i]);      // streaming: evict-first
        sumA += smap(v.x) + smap(v.y);
        sumB += smap(v.z) + smap(v.w);
        vmax = fmaxf(vmax, fmaxf(fmaxf(v.x, v.y), fmaxf(v.z, v.w)));
    }
    for (int i = (V4 << 2) + tid; i < V; i += nt) {
        float v = __ldcs(&x[i]);
        sumA += smap(v);
        vmax = fmaxf(vmax, v);
    }

    // ---- warp-shuffle reduce, then tiny cross-warp combine ----
    float wsumv = sumA + sumB;
    #pragma unroll
    for (int o = 16; o > 0; o >>= 1) {
        wsumv += __shfl_down_sync(0xffffffffu, wsumv, o);
        vmax   = fmaxf(vmax, __shfl_down_sync(0xffffffffu, vmax, o));
    }
    if (lane == 0) { wsum[wid] = wsumv; wmax[wid] = vmax; }
    __syncthreads();

    if (tid == 0) {
        float rs = wsum[0], rm = wmax[0];
        #pragma unroll
        for (int w = 1; w < 8; w++) { rs += wsum[w]; rm = fmaxf(rm, wmax[w]); }
        sh_sum = rs;
        sh_max = rm;

        long long label;
        if (g_labels_is64) label = ((const long long*)labels_raw)[row];
        else               label = (long long)((const int*)labels_raw)[row];
        int need = 0;
        if (label >= 0 && label < (long long)V) {
            float xl = x[(int)label];
            if (xl == rm) need = 1;      // label attains row max -> exact argmax
        }
        sh_need_scan = need;
    }
    __syncthreads();

    int arg_idx = -1;
    if (sh_need_scan) {
        // rare second pass: exact first-index argmax
        float lmax = -INFINITY;
        int   lidx = 0x7fffffff;
        for (int k = tid; k < V4; k += nt) {
            float4 v = __ldg(&x4[k]);
            int base = k << 2;
            if (v.x > lmax) { lmax = v.x; lidx = base + 0; }
            if (v.y > lmax) { lmax = v.y; lidx = base + 1; }
            if (v.z > lmax) { lmax = v.z; lidx = base + 2; }
            if (v.w > lmax) { lmax = v.w; lidx = base + 3; }
        }
        for (int k = (V4 << 2) + tid; k < V; k += nt) {
            float v = __ldg(&x[k]);
            if (v > lmax) { lmax = v; lidx = k; }
        }
        smaxv[tid] = lmax;
        sidx[tid]  = lidx;
        __syncthreads();
        for (int s = nt >> 1; s > 0; s >>= 1) {
            if (tid < s) {
                float mv = smaxv[tid + s]; int mi = sidx[tid + s];
                if (mv > smaxv[tid] || (mv == smaxv[tid] && mi < sidx[tid])) {
                    smaxv[tid] = mv; sidx[tid] = mi;
                }
            }
            __syncthreads();
        }
        arg_idx = sidx[0];
    }

    if (tid == 0) {
        long long label;
        if (g_labels_is64) label = ((const long long*)labels_raw)[row];
        else               label = (long long)((const int*)labels_raw)[row];

        if (label >= 0 && label < (long long)V) {
            int b = row / Lseq;
            double xd = (double)x[(int)label];
            double sl = xd < 0.0 ? 1.0 / (1.0 - xd + 1e-30) : xd + 1.0;
            double pt = log((double)sh_sum) - log(sl);   // -log(s_label/sum)
            atomicAdd(&g_tasksum[b], pt);
            atomicAdd(&g_valid[b], 1);
            bool correct = sh_need_scan && ((long long)arg_idx == label);
            if (correct) atomicAdd(&g_correct[b], 1);
        }

        // ---- last-block finalize ----
        __threadfence();
        unsigned int ticket = atomicAdd(&g_done, 1u);
        if (ticket == gridDim.x - 1) {
            volatile double* vsum = g_tasksum;
            volatile int*    vval = g_valid;
            volatile int*    vcor = g_correct;
            float Ltask = 0.f, lh = 0.f, lc = 0.f;
            for (int b = 0; b < Bn; b++) {
                int    nv = vval[b];
                int    nc = vcor[b];
                double ts = vsum[b];
                float cnt = (float)(nv > 1 ? nv : 1);
                Ltask += (float)ts / cnt;
                float t = (nc == nv) ? 1.f : 0.f;
                float xh = qh[b];
                lh += fmaxf(xh, 0.f) - xh * t + log1pf(expf(-fabsf(xh)));
                float tc = 1.f / (1.f + expf(-xh));
                float xc = qc[b];
                lc += fmaxf(xc, 0.f) - xc * tc + log1pf(expf(-fabsf(xc)));
                vsum[b] = 0.0;
                vval[b] = 0;
                vcor[b] = 0;
            }
            Ltask /= (float)Bn;
            float Lhalt = 0.5f * (lh / (float)Bn + lc / (float)Bn);
            out[0] = Ltask + Lhalt;
            __threadfence();
            g_done = 0;
        }
    }
}

extern "C" void kernel_launch(void* const* d_in, const int* in_sizes, int n_in,
                              void* d_out, int out_size) {
    // Identify inputs by size, not position.
    int li = 0;
    for (int i = 1; i < n_in; i++) if (in_sizes[i] > in_sizes[li]) li = i;
    int lab = -1;
    for (int i = 0; i < n_in; i++) {
        if (i == li) continue;
        if (lab < 0 || in_sizes[i] > in_sizes[lab]) lab = i;
    }
    int qi[2]; int nq = 0;
    for (int i = 0; i < n_in && nq < 2; i++) {
        if (i != li && i != lab) qi[nq++] = i;
    }

    const float* logits = (const float*)d_in[li];
    const void*  labels = d_in[lab];
    const float* qh     = (const float*)d_in[qi[0]];
    const float* qc     = (const float*)d_in[qi[1]];

    const int Bn   = in_sizes[qi[0]];
    const int rows = in_sizes[lab];
    const int Lseq = rows / Bn;
    const int V    = (int)((long long)in_sizes[li] / rows);

    probe_kernel<<<1, 32>>>(labels, V);
    row_kernel<<<rows, 256>>>(logits, labels, qh, qc, (float*)d_out, V, Lseq, Bn);
}